// round 11
// baseline (speedup 1.0000x reference)
#include <cuda_runtime.h>
#include <math.h>

#define Xd 32
#define Yd 16
#define Nn 8192          // 32*16*16
#define Cc 4
#define NITER 5
#define ALPHA 5.0f
#define BETA  5.0f
#define GAMMA 5.0f
#define DEG 7
#define RK 36            // #(i,j), i+j<=7
#define NBLK (RK * Cc + Cc)   // 148 co-resident blocks

typedef unsigned long long ull;

// shared layout (float offsets)
#define O_A   0                 // 8192: std input field
#define O_B   8192              // 9216: conv-x out (std) / conv-z out (padded 18)
#define O_P   17408             // 9216: conv-y out (padded 18)
#define O_TBL 26624
#define SMEM_FLOATS (26624 + 352)
#define SMEM_BYTES (SMEM_FLOATS * 4)

// ---- static device scratch ----
__device__ float g_phi[RK][Nn];      // phi, scaled in place to psi = phi*pre1
__device__ float g_e[Nn];
__device__ float g_pre1[Nn];
__device__ float g_pre2[Nn];
__device__ float g_part[NBLK][Nn];
__device__ float g_q[2][Cc][Nn];
__device__ unsigned g_arr[NBLK];
__device__ unsigned g_gen;

__device__ __forceinline__ void ffma2(ull& d, ull a, ull b) {
    asm("fma.rn.f32x2 %0, %1, %2, %0;" : "+l"(d) : "l"(a), "l"(b));
}
__device__ __forceinline__ float lo2(ull v) { return __uint_as_float((unsigned)v); }
__device__ __forceinline__ float hi2(ull v) { return __uint_as_float((unsigned)(v >> 32)); }

// ---- observer grid barrier (proven) ----
__device__ __forceinline__ void gbar(unsigned tgt, int b, int tid) {
    __syncthreads();
    if (b == 0) {
        if (tid == 0) { __threadfence(); *(volatile unsigned*)&g_arr[0] = tgt; }
        if (tid < NBLK) { while (*(volatile unsigned*)&g_arr[tid] < tgt) { } }
        __syncthreads();
        if (tid == 0) { __threadfence(); *(volatile unsigned*)&g_gen = tgt; }
    } else {
        if (tid == 0) {
            __threadfence();
            *(volatile unsigned*)&g_arr[b] = tgt;
            while (*(volatile unsigned*)&g_gen < tgt) { }
            __threadfence();
        }
        __syncthreads();
    }
}

// ---- separable 3D conv, all-FFMA2: in sm[O_A] (std) -> out sm[O_B] (padded 18) ----
// wx2/wy2: duplicated-pair tap tables (w[d],w[d]); Dz: consecutive-pair table.
__device__ __forceinline__ void conv3d(float* sm, const float* wx2, const float* wy2,
                                       const float* Dz, int tid) {
    float* sA = sm + O_A;
    float* sB = sm + O_B;
    float* sP = sm + O_P;
    __syncthreads();
    // conv-x: sA(std) -> sB(std). 512 threads, yz-pair lanes, 8 x-outputs/thread,
    // rolling 8 dup-weight regs. FMA and LDS both halved vs scalar reuse-8.
    if (tid < 512) {
        int xg = (tid >> 7) << 3;          // 4 groups: 0,8,16,24
        int yz = (tid & 127) << 1;         // yz pair
        ull acc[8] = {0,0,0,0,0,0,0,0};
        ull w[8];
#pragma unroll
        for (int k = 0; k < 8; k++) w[k] = *(const ull*)(wx2 + 2 * (xg + k));
#pragma unroll
        for (int xp = 0; xp < Xd; xp++) {
            ull v = *(const ull*)(sA + (xp << 8) + yz);
#pragma unroll
            for (int k = 0; k < 8; k++) ffma2(acc[k], w[k], v);
            if (xp < Xd - 1) {
#pragma unroll
                for (int k = 7; k >= 1; k--) w[k] = w[k - 1];
                int d = xg - xp - 1; if (d < 0) d = -d;
                w[0] = *(const ull*)(wx2 + 2 * d);
            }
        }
#pragma unroll
        for (int k = 0; k < 8; k++) *(ull*)(sB + ((xg + k) << 8) + yz) = acc[k];
    }
    __syncthreads();
    // conv-y: sB(std) -> sP(padded 18). 1024 threads, z-pair lanes, 4 y-outputs.
    {
        int unit = tid >> 2, q = tid & 3;
        int x = unit >> 3, zp = unit & 7;
        int ibase = (x << 8) + (zp << 1);
        int yg = q << 2;
        ull a0 = 0, a1 = 0, a2 = 0, a3 = 0;
        ull w0 = *(const ull*)(wy2 + 2 * (yg + 0));
        ull w1 = *(const ull*)(wy2 + 2 * (yg + 1));
        ull w2 = *(const ull*)(wy2 + 2 * (yg + 2));
        ull w3 = *(const ull*)(wy2 + 2 * (yg + 3));
#pragma unroll
        for (int yp = 0; yp < Yd; yp++) {
            ull v = *(const ull*)(sB + ibase + (yp << 4));
            ffma2(a0, w0, v); ffma2(a1, w1, v);
            ffma2(a2, w2, v); ffma2(a3, w3, v);
            if (yp < Yd - 1) {
                w3 = w2; w2 = w1; w1 = w0;
                int d = yg - yp - 1; if (d < 0) d = -d;
                w0 = *(const ull*)(wy2 + 2 * d);
            }
        }
        int obase = (x << 4) * 18 + (zp << 1);
        *(ull*)(sP + obase + (yg + 0) * 18) = a0;
        *(ull*)(sP + obase + (yg + 1) * 18) = a1;
        *(ull*)(sP + obase + (yg + 2) * 18) = a2;
        *(ull*)(sP + obase + (yg + 3) * 18) = a3;
    }
    __syncthreads();
    // conv-z: sP(padded) -> sB(padded). 2 threads/line, consecutive-pair weights.
    {
        int line = tid & 511, half = tid >> 9;
        const float* in = sP + line * 18;
        float* outp = sB + line * 18;
        ull v[8];
#pragma unroll
        for (int p = 0; p < 8; p++) v[p] = *(const ull*)(in + 2 * p);
        if (half == 0) {
#pragma unroll
            for (int zo = 0; zo < 8; zo++) {
                ull acc = 0;
#pragma unroll
                for (int p = 0; p < 8; p++)
                    ffma2(acc, *(const ull*)(Dz + 2 * (zo - 2 * p + 14)), v[p]);
                outp[zo] = lo2(acc) + hi2(acc);
            }
        } else {
#pragma unroll
            for (int zo = 8; zo < 16; zo++) {
                ull acc = 0;
#pragma unroll
                for (int p = 0; p < 8; p++)
                    ffma2(acc, *(const ull*)(Dz + 2 * (zo - 2 * p + 14)), v[p]);
                outp[zo] = lo2(acc) + hi2(acc);
            }
        }
    }
    __syncthreads();
}

#define CONVOUT(sm, n) ((sm)[O_B + ((n) >> 4) * 18 + ((n) & 15)])

__global__ __launch_bounds__(1024, 1) void k_crf(
    const float* __restrict__ lu, const float* __restrict__ fp,
    const float* __restrict__ comp, float* __restrict__ out) {
    extern __shared__ float sm[];
    float* s_wax2 = sm + O_TBL;        // 64: bilateral x dup pairs
    float* s_wgx2 = s_wax2 + 64;       // 64: spatial x dup pairs
    float* s_way2 = s_wgx2 + 64;       // 32: bilateral y dup pairs
    float* s_wgy2 = s_way2 + 32;       // 32: spatial y dup pairs
    float* s_Da   = s_wgy2 + 32;       // bilateral z pair table (j=-14..15)
    float* s_Dg   = s_Da + 64;         // spatial z pair table
    float* s_cmp  = s_Dg + 64;         // 16
    __shared__ unsigned s_base;

    int tid = threadIdx.x;
    int b = blockIdx.x;

    if (tid == 0) s_base = *(volatile unsigned*)&g_arr[b];
    if (tid < 32) {
        float d2 = (float)tid * (float)tid;
        float wa = __expf(-0.5f * d2 / (ALPHA * ALPHA));
        float wg = __expf(-0.5f * d2 / (GAMMA * GAMMA));
        s_wax2[2 * tid] = wa; s_wax2[2 * tid + 1] = wa;
        s_wgx2[2 * tid] = wg; s_wgx2[2 * tid + 1] = wg;
        if (tid < 16) {
            s_way2[2 * tid] = wa; s_way2[2 * tid + 1] = wa;
            s_wgy2[2 * tid] = wg; s_wgy2[2 * tid + 1] = wg;
            s_cmp[tid] = comp[tid];
        }
    }
    if (tid < 30) {                    // D[t] = (w|j|, w|j-1|), j = t-14
        int j = tid - 14;
        int a0 = j < 0 ? -j : j;
        int a1 = j - 1 < 0 ? 1 - j : j - 1;
        s_Da[2 * tid]     = __expf(-0.5f * (float)(a0 * a0) / (ALPHA * ALPHA));
        s_Da[2 * tid + 1] = __expf(-0.5f * (float)(a1 * a1) / (ALPHA * ALPHA));
        s_Dg[2 * tid]     = __expf(-0.5f * (float)(a0 * a0) / (GAMMA * GAMMA));
        s_Dg[2 * tid + 1] = __expf(-0.5f * (float)(a1 * a1) / (GAMMA * GAMMA));
    }
    __syncthreads();
    unsigned base = s_base, bk = 0;

    // ==== phase A || B ====
    if (b < RK) {
        int i = 0, rr = b;
        while (rr > DEG - i) { rr -= DEG - i + 1; i++; }
        int j = rr;
        float fi = 1.f, fj = 1.f;
        for (int t = 2; t <= i; t++) fi *= (float)t;
        for (int t = 2; t <= j; t++) fj *= (float)t;
        float coef = rsqrtf(fi * fj);
        float ph[8];
#pragma unroll
        for (int u = 0; u < 8; u++) {
            int n = (u << 10) + tid;
            float fa = fp[n] * (1.0f / BETA);
            float fb = fp[Nn + n] * (1.0f / BETA);
            float e = __expf(-0.5f * (fa * fa + fb * fb));
            float pa = 1.f, pb = 1.f;
            for (int t = 0; t < i; t++) pa *= fa;
            for (int t = 0; t < j; t++) pb *= fb;
            ph[u] = coef * pa * pb;
            sm[O_A + n] = ph[u] * e;
        }
        conv3d(sm, s_wax2, s_way2, s_Da, tid);
#pragma unroll
        for (int u = 0; u < 8; u++) {
            int n = (u << 10) + tid;
            g_part[b][n] = ph[u] * CONVOUT(sm, n);
        }
    } else if (b < RK + 64) {
        if (tid < 128) {
            int n = ((b - RK) << 7) + tid;
            float fa = fp[n] * (1.0f / BETA);
            float fb = fp[Nn + n] * (1.0f / BETA);
            float e = __expf(-0.5f * (fa * fa + fb * fb));
            g_e[n] = e;
            float fi = 1.f, pai = 1.f;
            int r = 0;
#pragma unroll
            for (int i = 0; i <= DEG; i++) {
                if (i > 0) fi *= (float)i;
                float fj = 1.f, pbj = 1.f;
#pragma unroll
                for (int j = 0; j <= DEG - i; j++) {
                    if (j > 0) fj *= (float)j;
                    g_phi[r][n] = rsqrtf(fi * fj) * pai * pbj;
                    pbj *= fb;
                    r++;
                }
                pai *= fa;
            }
            float l0 = lu[n], l1 = lu[Nn + n], l2 = lu[2 * Nn + n], l3 = lu[3 * Nn + n];
            float mx = fmaxf(fmaxf(l0, l1), fmaxf(l2, l3));
            float e0 = __expf(l0 - mx), e1 = __expf(l1 - mx);
            float e2 = __expf(l2 - mx), e3 = __expf(l3 - mx);
            float inv = 1.0f / (e0 + e1 + e2 + e3);
            g_q[0][0][n] = e0 * inv; g_q[0][1][n] = e1 * inv;
            g_q[0][2][n] = e2 * inv; g_q[0][3][n] = e3 * inv;
        }
    }
    gbar(base + (++bk), b, tid);

    // ==== phase C: normalization scales ====
    if (b < 32 && tid < 256) {
        int n = (b << 8) + tid;
        float s = 0.f;
#pragma unroll
        for (int r = 0; r < RK; r++) s += __ldcg(&g_part[r][n]);
        float e = g_e[n];
        g_pre1[n] = e * rsqrtf(e * s);
        int x = n >> 8, y = (n >> 4) & 15, z = n & 15;
        float Rx = 0.f, Ry = 0.f, Rz = 0.f;
#pragma unroll
        for (int d = 0; d < Xd; d++) Rx += s_wgx2[2 * ((x > d) ? (x - d) : (d - x))];
#pragma unroll
        for (int d = 0; d < Yd; d++) {
            Ry += s_wgy2[2 * ((y > d) ? (y - d) : (d - y))];
            Rz += s_wgy2[2 * ((z > d) ? (z - d) : (d - z))];
        }
        g_pre2[n] = rsqrtf(Rx * Ry * Rz);
    }
    gbar(base + (++bk), b, tid);

    // ==== phase D: psi = phi * pre1 in place ====
    if (b < RK) {
#pragma unroll
        for (int u = 0; u < 8; u++) {
            int n = (u << 10) + tid;
            g_phi[b][n] *= g_pre1[n];
        }
    }
    gbar(base + (++bk), b, tid);

    // ==== phase E: 5 mean-field iterations ====
    int r = b >> 2, c = b & 3;
    bool sp = (r == RK);
    const float4* mul4 = sp ? (const float4*)g_pre2 : (const float4*)g_phi[r];
    const float* wxE = sp ? s_wgx2 : s_wax2;
    const float* wyE = sp ? s_wgy2 : s_way2;
    const float* DzE = sp ? s_Dg : s_Da;
    // hoisted update-phase state (R10-proven layout)
    int uc = 0, un = 0, ulv = 0;
    float lu0 = 0.f, lu1 = 0.f, lu2 = 0.f, lu3 = 0.f;
    if (b < 32) {
        int warp = tid >> 5, lane = tid & 31;
        uc = warp & 3;
        ulv = ((warp >> 2) << 5) + lane;
        un = (b << 8) + ulv;
        lu0 = lu[un]; lu1 = lu[Nn + un]; lu2 = lu[2 * Nn + un]; lu3 = lu[3 * Nn + un];
    }
    for (int it = 0; it < NITER; it++) {
        {
            const float4* q4 = (const float4*)g_q[it & 1][c];
            float4* sa4 = (float4*)(sm + O_A);
#pragma unroll
            for (int u = 0; u < 2; u++) {
                int i4 = tid * 2 + u;
                float4 M = mul4[i4];
                float4 Q = __ldcg(q4 + i4);
                sa4[i4] = make_float4(M.x * Q.x, M.y * Q.y, M.z * Q.z, M.w * Q.w);
            }
            conv3d(sm, wxE, wyE, DzE, tid);
            float4* dst = (float4*)g_part[b];
#pragma unroll
            for (int u = 0; u < 2; u++) {
                int i4 = tid * 2 + u;
                float4 M = mul4[i4];
                int n0 = i4 << 2;
                dst[i4] = make_float4(M.x * CONVOUT(sm, n0),
                                      M.y * CONVOUT(sm, n0 + 1),
                                      M.z * CONVOUT(sm, n0 + 2),
                                      M.w * CONVOUT(sm, n0 + 3));
            }
        }
        gbar(base + (++bk), b, tid);
        // ==== update (R10-proven): warp-coalesced k-sweep + smem exchange ====
        if (b < 32) {
            float u = 0.f;
#pragma unroll
            for (int k = 0; k <= RK; k++)
                u += __ldcg(&g_part[k * 4 + uc][un]);
            sm[O_A + uc * 256 + ulv] = u;
            __syncthreads();
            float u0 = sm[O_A + 0 * 256 + ulv], u1 = sm[O_A + 1 * 256 + ulv];
            float u2 = sm[O_A + 2 * 256 + ulv], u3 = sm[O_A + 3 * 256 + ulv];
            float lg0 = lu0 - (s_cmp[0] * u0 + s_cmp[1] * u1 + s_cmp[2] * u2 + s_cmp[3] * u3);
            float lg1 = lu1 - (s_cmp[4] * u0 + s_cmp[5] * u1 + s_cmp[6] * u2 + s_cmp[7] * u3);
            float lg2 = lu2 - (s_cmp[8] * u0 + s_cmp[9] * u1 + s_cmp[10] * u2 + s_cmp[11] * u3);
            float lg3 = lu3 - (s_cmp[12] * u0 + s_cmp[13] * u1 + s_cmp[14] * u2 + s_cmp[15] * u3);
            float mx = fmaxf(fmaxf(lg0, lg1), fmaxf(lg2, lg3));
            float e0 = __expf(lg0 - mx), e1 = __expf(lg1 - mx);
            float e2 = __expf(lg2 - mx), e3 = __expf(lg3 - mx);
            float inv = 1.0f / (e0 + e1 + e2 + e3);
            float qv = (uc == 0 ? e0 : uc == 1 ? e1 : uc == 2 ? e2 : e3) * inv;
            if (it == NITER - 1) out[uc * Nn + un] = qv;
            else                 g_q[(it + 1) & 1][uc][un] = qv;
        }
        if (it < NITER - 1) gbar(base + (++bk), b, tid);
    }
}

extern "C" void kernel_launch(void* const* d_in, const int* in_sizes, int n_in,
                              void* d_out, int out_size) {
    const float* lu   = (const float*)d_in[0];
    const float* fp   = (const float*)d_in[1];
    const float* comp = (const float*)d_in[2];
    float* out = (float*)d_out;

    cudaFuncSetAttribute(k_crf, cudaFuncAttributeMaxDynamicSharedMemorySize, SMEM_BYTES);
    k_crf<<<NBLK, 1024, SMEM_BYTES>>>(lu, fp, comp, out);
}

// round 12
// speedup vs baseline: 1.0738x; 1.0738x over previous
#include <cuda_runtime.h>
#include <math.h>

#define Xd 32
#define Yd 16
#define Nn 8192          // 32*16*16
#define Cc 4
#define NITER 5
#define ALPHA 5.0f
#define BETA  5.0f
#define GAMMA 5.0f
#define DEG 7
#define RK 36            // #(i,j), i+j<=7
#define NBLK (RK * Cc + Cc)   // 148 co-resident blocks

// shared layout (float offsets)
#define O_A   0                 // 8704: std input (first 8192) / conv-z out (pad 17)
#define O_B   8704              // 8192: conv-x out (std)
#define O_P   16896             // 8704: conv-y out (pad 17)
#define O_TBL 25600
#define SMEM_FLOATS (25600 + 128)
#define SMEM_BYTES (SMEM_FLOATS * 4)

// ---- static device scratch ----
__device__ float g_phi[RK][Nn];      // phi, scaled in place to psi = phi*pre1
__device__ float g_e[Nn];
__device__ float g_pre1[Nn];
__device__ float g_pre2[Nn];
__device__ float g_part[NBLK][Nn];
__device__ float g_q[2][Cc][Nn];
__device__ unsigned g_arr[NBLK];
__device__ unsigned g_gen;

// ---- observer grid barrier (proven) ----
__device__ __forceinline__ void gbar(unsigned tgt, int b, int tid) {
    __syncthreads();
    if (b == 0) {
        if (tid == 0) { __threadfence(); *(volatile unsigned*)&g_arr[0] = tgt; }
        if (tid < NBLK) { while (*(volatile unsigned*)&g_arr[tid] < tgt) { } }
        __syncthreads();
        if (tid == 0) { __threadfence(); *(volatile unsigned*)&g_gen = tgt; }
    } else {
        if (tid == 0) {
            __threadfence();
            *(volatile unsigned*)&g_arr[b] = tgt;
            while (*(volatile unsigned*)&g_gen < tgt) { }
            __threadfence();
        }
        __syncthreads();
    }
}

// ---- separable 3D conv: in sm[O_A] (std) -> out sm[O_A] (pad 17) ----
// All stages: register-lean rolling-window, 1024 active threads.
__device__ __forceinline__ void conv3d(float* sm, const float* wx, const float* wyz,
                                       int tid) {
    float* sA = sm + O_A;
    float* sB = sm + O_B;
    float* sP = sm + O_P;
    __syncthreads();
    // conv-x: sA(std) -> sB(std). 8 outputs/thread, rolling 8-weight window.
    {
        int xg = (tid >> 8) << 3;
        int yz = tid & 255;
        float acc[8] = {0.f,0.f,0.f,0.f,0.f,0.f,0.f,0.f};
        float w[8];
#pragma unroll
        for (int k = 0; k < 8; k++) w[k] = wx[xg + k];
#pragma unroll
        for (int xp = 0; xp < Xd; xp++) {
            float v = sA[(xp << 8) + yz];
#pragma unroll
            for (int k = 0; k < 8; k++) acc[k] += w[k] * v;
            if (xp < Xd - 1) {
#pragma unroll
                for (int k = 7; k >= 1; k--) w[k] = w[k - 1];
                int d = xg - xp - 1; if (d < 0) d = -d;
                w[0] = wx[d];
            }
        }
#pragma unroll
        for (int k = 0; k < 8; k++) sB[((xg + k) << 8) + yz] = acc[k];
    }
    __syncthreads();
    // conv-y: sB(std) -> sP(pad 17). thread=(x, z, yg-half), 8 y-outputs, rolling.
    {
        int x = tid >> 5, rem = tid & 31;
        int z = rem & 15, yg = (rem >> 4) << 3;
        float acc[8] = {0.f,0.f,0.f,0.f,0.f,0.f,0.f,0.f};
        float w[8];
#pragma unroll
        for (int k = 0; k < 8; k++) w[k] = wyz[yg + k];
#pragma unroll
        for (int yp = 0; yp < Yd; yp++) {
            float v = sB[(x << 8) + (yp << 4) + z];
#pragma unroll
            for (int k = 0; k < 8; k++) acc[k] += w[k] * v;
            if (yp < Yd - 1) {
#pragma unroll
                for (int k = 7; k >= 1; k--) w[k] = w[k - 1];
                int d = yg - yp - 1; if (d < 0) d = -d;
                w[0] = wyz[d];
            }
        }
        int ob = x << 4;
#pragma unroll
        for (int k = 0; k < 8; k++) sP[(ob + yg + k) * 17 + z] = acc[k];
    }
    __syncthreads();
    // conv-z: sP(pad 17) -> sA(pad 17). 2 threads/line, 8 z-outputs, rolling.
    // stride 17 coprime to 32 -> conflict-free scalar line reads.
    {
        int line = tid >> 1;
        int zg = (tid & 1) << 3;
        const float* in = sP + line * 17;
        float acc[8] = {0.f,0.f,0.f,0.f,0.f,0.f,0.f,0.f};
        float w[8];
#pragma unroll
        for (int k = 0; k < 8; k++) w[k] = wyz[zg + k];
#pragma unroll
        for (int zp = 0; zp < 16; zp++) {
            float v = in[zp];
#pragma unroll
            for (int k = 0; k < 8; k++) acc[k] += w[k] * v;
            if (zp < 15) {
#pragma unroll
                for (int k = 7; k >= 1; k--) w[k] = w[k - 1];
                int d = zg - zp - 1; if (d < 0) d = -d;
                w[0] = wyz[d];
            }
        }
        float* o = sA + line * 17 + zg;
#pragma unroll
        for (int k = 0; k < 8; k++) o[k] = acc[k];
    }
    __syncthreads();
}

#define CONVOUT(sm, n) ((sm)[O_A + ((n) >> 4) * 17 + ((n) & 15)])

__global__ __launch_bounds__(1024, 1) void k_crf(
    const float* __restrict__ lu, const float* __restrict__ fp,
    const float* __restrict__ comp, float* __restrict__ out) {
    extern __shared__ float sm[];
    float* s_wax = sm + O_TBL;         // 32
    float* s_way = s_wax + 32;         // 16
    float* s_wgx = s_way + 16;         // 32
    float* s_wgy = s_wgx + 32;         // 16
    float* s_cmp = s_wgy + 16;         // 16
    __shared__ unsigned s_base;

    int tid = threadIdx.x;
    int b = blockIdx.x;

    if (tid == 0) s_base = *(volatile unsigned*)&g_arr[b];
    if (tid < 32) {
        float d2 = (float)tid * (float)tid;
        s_wax[tid] = __expf(-0.5f * d2 / (ALPHA * ALPHA));
        s_wgx[tid] = __expf(-0.5f * d2 / (GAMMA * GAMMA));
    }
    if (tid < 16) {
        float d2 = (float)tid * (float)tid;
        s_way[tid] = __expf(-0.5f * d2 / (ALPHA * ALPHA));
        s_wgy[tid] = __expf(-0.5f * d2 / (GAMMA * GAMMA));
        s_cmp[tid] = comp[tid];
    }
    __syncthreads();
    unsigned base = s_base, bk = 0;

    // ==== phase A || B ====
    if (b < RK) {
        int i = 0, rr = b;
        while (rr > DEG - i) { rr -= DEG - i + 1; i++; }
        int j = rr;
        float fi = 1.f, fj = 1.f;
        for (int t = 2; t <= i; t++) fi *= (float)t;
        for (int t = 2; t <= j; t++) fj *= (float)t;
        float coef = rsqrtf(fi * fj);
        float ph[8];
#pragma unroll
        for (int u = 0; u < 8; u++) {
            int n = (u << 10) + tid;
            float fa = fp[n] * (1.0f / BETA);
            float fb = fp[Nn + n] * (1.0f / BETA);
            float e = __expf(-0.5f * (fa * fa + fb * fb));
            float pa = 1.f, pb = 1.f;
            for (int t = 0; t < i; t++) pa *= fa;
            for (int t = 0; t < j; t++) pb *= fb;
            ph[u] = coef * pa * pb;
            sm[O_A + n] = ph[u] * e;
        }
        conv3d(sm, s_wax, s_way, tid);
#pragma unroll
        for (int u = 0; u < 8; u++) {
            int n = (u << 10) + tid;
            g_part[b][n] = ph[u] * CONVOUT(sm, n);
        }
    } else if (b < RK + 64) {
        if (tid < 128) {
            int n = ((b - RK) << 7) + tid;
            float fa = fp[n] * (1.0f / BETA);
            float fb = fp[Nn + n] * (1.0f / BETA);
            float e = __expf(-0.5f * (fa * fa + fb * fb));
            g_e[n] = e;
            float fi = 1.f, pai = 1.f;
            int r = 0;
#pragma unroll
            for (int i = 0; i <= DEG; i++) {
                if (i > 0) fi *= (float)i;
                float fj = 1.f, pbj = 1.f;
#pragma unroll
                for (int j = 0; j <= DEG - i; j++) {
                    if (j > 0) fj *= (float)j;
                    g_phi[r][n] = rsqrtf(fi * fj) * pai * pbj;
                    pbj *= fb;
                    r++;
                }
                pai *= fa;
            }
            float l0 = lu[n], l1 = lu[Nn + n], l2 = lu[2 * Nn + n], l3 = lu[3 * Nn + n];
            float mx = fmaxf(fmaxf(l0, l1), fmaxf(l2, l3));
            float e0 = __expf(l0 - mx), e1 = __expf(l1 - mx);
            float e2 = __expf(l2 - mx), e3 = __expf(l3 - mx);
            float inv = 1.0f / (e0 + e1 + e2 + e3);
            g_q[0][0][n] = e0 * inv; g_q[0][1][n] = e1 * inv;
            g_q[0][2][n] = e2 * inv; g_q[0][3][n] = e3 * inv;
        }
    }
    gbar(base + (++bk), b, tid);

    // ==== phase C: normalization scales ====
    if (b < 32 && tid < 256) {
        int n = (b << 8) + tid;
        float s = 0.f;
#pragma unroll
        for (int r = 0; r < RK; r++) s += __ldcg(&g_part[r][n]);
        float e = g_e[n];
        g_pre1[n] = e * rsqrtf(e * s);
        int x = n >> 8, y = (n >> 4) & 15, z = n & 15;
        float Rx = 0.f, Ry = 0.f, Rz = 0.f;
#pragma unroll
        for (int d = 0; d < Xd; d++) Rx += s_wgx[(x > d) ? (x - d) : (d - x)];
#pragma unroll
        for (int d = 0; d < Yd; d++) {
            Ry += s_wgy[(y > d) ? (y - d) : (d - y)];
            Rz += s_wgy[(z > d) ? (z - d) : (d - z)];
        }
        g_pre2[n] = rsqrtf(Rx * Ry * Rz);
    }
    gbar(base + (++bk), b, tid);

    // ==== phase D: psi = phi * pre1 in place ====
    if (b < RK) {
#pragma unroll
        for (int u = 0; u < 8; u++) {
            int n = (u << 10) + tid;
            g_phi[b][n] *= g_pre1[n];
        }
    }
    gbar(base + (++bk), b, tid);

    // ==== phase E: 5 mean-field iterations ====
    int r = b >> 2, c = b & 3;
    bool sp = (r == RK);
    const float4* mul4 = sp ? (const float4*)g_pre2 : (const float4*)g_phi[r];
    const float* wxE = sp ? s_wgx : s_wax;
    const float* wyE = sp ? s_wgy : s_way;
    for (int it = 0; it < NITER; it++) {
        {
            const float4* q4 = (const float4*)g_q[it & 1][c];
            float4* sa4 = (float4*)(sm + O_A);
#pragma unroll
            for (int u = 0; u < 2; u++) {
                int i4 = tid * 2 + u;
                float4 M = mul4[i4];          // immutable after phase D
                float4 Q = __ldcg(q4 + i4);   // mutable: L2-coherent
                sa4[i4] = make_float4(M.x * Q.x, M.y * Q.y, M.z * Q.z, M.w * Q.w);
            }
            conv3d(sm, wxE, wyE, tid);
            float4* dst = (float4*)g_part[b];
#pragma unroll
            for (int u = 0; u < 2; u++) {
                int i4 = tid * 2 + u;
                float4 M = mul4[i4];
                int n0 = i4 << 2;
                dst[i4] = make_float4(M.x * CONVOUT(sm, n0),
                                      M.y * CONVOUT(sm, n0 + 1),
                                      M.z * CONVOUT(sm, n0 + 2),
                                      M.w * CONVOUT(sm, n0 + 3));
            }
        }
        gbar(base + (++bk), b, tid);
        // ==== update (R10-proven layout; state recomputed per iteration) ====
        if (b < 32) {
            int warp = tid >> 5, lane = tid & 31;
            int uc = warp & 3;
            int ulv = ((warp >> 2) << 5) + lane;
            int un = (b << 8) + ulv;
            float u = 0.f;
#pragma unroll
            for (int k = 0; k <= RK; k++)
                u += __ldcg(&g_part[k * 4 + uc][un]);
            sm[O_A + uc * 256 + ulv] = u;
            __syncthreads();
            float u0 = sm[O_A + 0 * 256 + ulv], u1 = sm[O_A + 1 * 256 + ulv];
            float u2 = sm[O_A + 2 * 256 + ulv], u3 = sm[O_A + 3 * 256 + ulv];
            float lg0 = lu[un]          - (s_cmp[0] * u0 + s_cmp[1] * u1 + s_cmp[2] * u2 + s_cmp[3] * u3);
            float lg1 = lu[Nn + un]     - (s_cmp[4] * u0 + s_cmp[5] * u1 + s_cmp[6] * u2 + s_cmp[7] * u3);
            float lg2 = lu[2 * Nn + un] - (s_cmp[8] * u0 + s_cmp[9] * u1 + s_cmp[10] * u2 + s_cmp[11] * u3);
            float lg3 = lu[3 * Nn + un] - (s_cmp[12] * u0 + s_cmp[13] * u1 + s_cmp[14] * u2 + s_cmp[15] * u3);
            float mx = fmaxf(fmaxf(lg0, lg1), fmaxf(lg2, lg3));
            float e0 = __expf(lg0 - mx), e1 = __expf(lg1 - mx);
            float e2 = __expf(lg2 - mx), e3 = __expf(lg3 - mx);
            float inv = 1.0f / (e0 + e1 + e2 + e3);
            float qv = (uc == 0 ? e0 : uc == 1 ? e1 : uc == 2 ? e2 : e3) * inv;
            if (it == NITER - 1) out[uc * Nn + un] = qv;
            else                 g_q[(it + 1) & 1][uc][un] = qv;
        }
        if (it < NITER - 1) gbar(base + (++bk), b, tid);
    }
}

extern "C" void kernel_launch(void* const* d_in, const int* in_sizes, int n_in,
                              void* d_out, int out_size) {
    const float* lu   = (const float*)d_in[0];
    const float* fp   = (const float*)d_in[1];
    const float* comp = (const float*)d_in[2];
    float* out = (float*)d_out;

    cudaFuncSetAttribute(k_crf, cudaFuncAttributeMaxDynamicSharedMemorySize, SMEM_BYTES);
    k_crf<<<NBLK, 1024, SMEM_BYTES>>>(lu, fp, comp, out);
}

// round 13
// speedup vs baseline: 1.2183x; 1.1346x over previous
#include <cuda_runtime.h>
#include <math.h>

#define Xd 32
#define Yd 16
#define Nn 8192          // 32*16*16
#define Cc 4
#define NITER 5
#define ALPHA 5.0f
#define BETA  5.0f
#define GAMMA 5.0f
#define DEG 4            // Taylor truncation (measured sensitivity ~20x/degree)
#define RK 15            // #(i,j), i+j<=4
#define NTASK (RK * Cc + Cc)  // 64 conv tasks
#define NBLK (NTASK * 2)      // 128 blocks: 2 per task (input z-halves)

// shared layout (float offsets)
#define O_IN  0                 // 4096: input half field, idx = line*8 + zl
#define O_CX  4096              // 4352: conv-x out, idx = x*136 + y*8 + zl
#define O_CY  8448              // 5120: conv-y out, idx = line*10 + zl
#define O_CZ  13568             // 8704: conv-z out (full field), idx = line*17 + z
#define O_TBL 22272
#define SMEM_FLOATS (22272 + 128)
#define SMEM_BYTES (SMEM_FLOATS * 4)

// ---- static device scratch ----
__device__ float g_phi[RK][Nn];      // phi, scaled in place to psi = phi*pre1
__device__ float g_e[Nn];
__device__ float g_pre1[Nn];
__device__ float g_pre2[Nn];
__device__ float g_part[NBLK][Nn];   // per-block partial planes (halves sum in update)
__device__ float g_q[2][Cc][Nn];
__device__ unsigned g_arr[NBLK];
__device__ unsigned g_gen;

// ---- observer grid barrier (proven) ----
__device__ __forceinline__ void gbar(unsigned tgt, int b, int tid) {
    __syncthreads();
    if (b == 0) {
        if (tid == 0) { __threadfence(); *(volatile unsigned*)&g_arr[0] = tgt; }
        if (tid < NBLK) { while (*(volatile unsigned*)&g_arr[tid] < tgt) { } }
        __syncthreads();
        if (tid == 0) { __threadfence(); *(volatile unsigned*)&g_gen = tgt; }
    } else {
        if (tid == 0) {
            __threadfence();
            *(volatile unsigned*)&g_arr[b] = tgt;
            while (*(volatile unsigned*)&g_gen < tgt) { }
            __threadfence();
        }
        __syncthreads();
    }
}

// ---- half-input separable conv: sm[O_IN] (z-half h) -> sm[O_CZ] (full-z partial) ----
__device__ __forceinline__ void conv3d_half(float* sm, const float* wx,
                                            const float* wyz, int h, int tid) {
    float* sI = sm + O_IN;
    float* sX = sm + O_CX;
    float* sY = sm + O_CY;
    float* sZ = sm + O_CZ;
    __syncthreads();
    // conv-x: sI -> sX. 8 groups of 4 x-outputs; 128 (y,zl) positions.
    {
        int xg = (tid >> 7) << 2;
        int pos = tid & 127;
        float a0 = 0.f, a1 = 0.f, a2 = 0.f, a3 = 0.f;
        float w0 = wx[xg], w1 = wx[xg + 1], w2 = wx[xg + 2], w3 = wx[xg + 3];
#pragma unroll
        for (int xp = 0; xp < Xd; xp++) {
            float v = sI[(xp << 7) + pos];
            a0 += w0 * v; a1 += w1 * v; a2 += w2 * v; a3 += w3 * v;
            if (xp < Xd - 1) {
                w3 = w2; w2 = w1; w1 = w0;
                int d = xg - xp - 1; if (d < 0) d = -d;
                w0 = wx[d];
            }
        }
        sX[(xg + 0) * 136 + pos] = a0;
        sX[(xg + 1) * 136 + pos] = a1;
        sX[(xg + 2) * 136 + pos] = a2;
        sX[(xg + 3) * 136 + pos] = a3;
    }
    __syncthreads();
    // conv-y: sX -> sY. thread = (x, zl, yq); 4 y-outputs.
    {
        int x = tid >> 5, rem = tid & 31;
        int zl = rem & 7, yg = (rem >> 3) << 2;
        float a0 = 0.f, a1 = 0.f, a2 = 0.f, a3 = 0.f;
        float w0 = wyz[yg], w1 = wyz[yg + 1], w2 = wyz[yg + 2], w3 = wyz[yg + 3];
#pragma unroll
        for (int yp = 0; yp < Yd; yp++) {
            float v = sX[x * 136 + (yp << 3) + zl];
            a0 += w0 * v; a1 += w1 * v; a2 += w2 * v; a3 += w3 * v;
            if (yp < Yd - 1) {
                w3 = w2; w2 = w1; w1 = w0;
                int d = yg - yp - 1; if (d < 0) d = -d;
                w0 = wyz[d];
            }
        }
        int lb = (x << 4) + yg;
        sY[(lb + 0) * 10 + zl] = a0;
        sY[(lb + 1) * 10 + zl] = a1;
        sY[(lb + 2) * 10 + zl] = a2;
        sY[(lb + 3) * 10 + zl] = a3;
    }
    __syncthreads();
    // conv-z (partial over input half): sY -> sZ. 2 threads/line, 8 z-outputs each.
    // output zo = zg+k (global), input zi = h*8+zl; weight = wyz[|zo - zi|].
    {
        int line = tid >> 1;
        int zg = (tid & 1) << 3;
        int zz = zg - (h << 3);              // -8, 0, or 8
        const float* in = sY + line * 10;
        float acc[8] = {0.f,0.f,0.f,0.f,0.f,0.f,0.f,0.f};
        float w[8];
#pragma unroll
        for (int k = 0; k < 8; k++) {
            int d = zz + k; if (d < 0) d = -d;
            w[k] = wyz[d];
        }
#pragma unroll
        for (int zl = 0; zl < 8; zl++) {
            float v = in[zl];
#pragma unroll
            for (int k = 0; k < 8; k++) acc[k] += w[k] * v;
            if (zl < 7) {
#pragma unroll
                for (int k = 7; k >= 1; k--) w[k] = w[k - 1];
                int d = zz - zl - 1; if (d < 0) d = -d;
                w[0] = wyz[d];
            }
        }
        float* o = sZ + line * 17 + zg;
#pragma unroll
        for (int k = 0; k < 8; k++) o[k] = acc[k];
    }
    __syncthreads();
}

#define CONVOUT(sm, n) ((sm)[O_CZ + ((n) >> 4) * 17 + ((n) & 15)])

__global__ __launch_bounds__(1024, 1) void k_crf(
    const float* __restrict__ lu, const float* __restrict__ fp,
    const float* __restrict__ comp, float* __restrict__ out) {
    extern __shared__ float sm[];
    float* s_wax = sm + O_TBL;         // 32
    float* s_way = s_wax + 32;         // 16
    float* s_wgx = s_way + 16;         // 32
    float* s_wgy = s_wgx + 32;         // 16
    float* s_cmp = s_wgy + 16;         // 16
    __shared__ unsigned s_base;

    int tid = threadIdx.x;
    int b = blockIdx.x;

    if (tid == 0) s_base = *(volatile unsigned*)&g_arr[b];
    if (tid < 32) {
        float d2 = (float)tid * (float)tid;
        s_wax[tid] = __expf(-0.5f * d2 / (ALPHA * ALPHA));
        s_wgx[tid] = __expf(-0.5f * d2 / (GAMMA * GAMMA));
    }
    if (tid < 16) {
        float d2 = (float)tid * (float)tid;
        s_way[tid] = __expf(-0.5f * d2 / (ALPHA * ALPHA));
        s_wgy[tid] = __expf(-0.5f * d2 / (GAMMA * GAMMA));
        s_cmp[tid] = comp[tid];
    }
    __syncthreads();
    unsigned base = s_base, bk = 0;

    // block role: task = b>>1, h = b&1
    int task = b >> 1, h = b & 1;

    // ==== phase A || B (concurrent) ====
    if (b < 2 * RK) {
        // B: partial rowsum conv for rank (task), input half h.
        int i = 0, rr = task;
        while (rr > DEG - i) { rr -= DEG - i + 1; i++; }
        int j = rr;
        float fi = 1.f, fj = 1.f;
        for (int t = 2; t <= i; t++) fi *= (float)t;
        for (int t = 2; t <= j; t++) fj *= (float)t;
        float coef = rsqrtf(fi * fj);
        // prologue: phi*e on half positions
        {
            int line = tid >> 1, q4 = tid & 1;
            int n0 = ((line << 2) + (h << 1) + q4) << 2;
#pragma unroll
            for (int el = 0; el < 4; el++) {
                int n = n0 + el;
                float fa = fp[n] * (1.0f / BETA);
                float fb = fp[Nn + n] * (1.0f / BETA);
                float e = __expf(-0.5f * (fa * fa + fb * fb));
                float pa = 1.f, pb = 1.f;
                for (int t = 0; t < i; t++) pa *= fa;
                for (int t = 0; t < j; t++) pb *= fb;
                sm[O_IN + (line << 3) + (q4 << 2) + el] = coef * pa * pb * e;
            }
        }
        conv3d_half(sm, s_wax, s_way, h, tid);
        // epilogue: full-field phi * partial conv
#pragma unroll
        for (int u = 0; u < 2; u++) {
            int n0 = (tid * 2 + u) << 2;
#pragma unroll
            for (int el = 0; el < 4; el++) {
                int n = n0 + el;
                float fa = fp[n] * (1.0f / BETA);
                float fb = fp[Nn + n] * (1.0f / BETA);
                float pa = 1.f, pb = 1.f;
                for (int t = 0; t < i; t++) pa *= fa;
                for (int t = 0; t < j; t++) pb *= fb;
                g_part[b][n] = coef * pa * pb * CONVOUT(sm, n);
            }
        }
    } else if (b < 2 * RK + 64) {
        // A: phi basis, e, q0 (64 blocks x 128 voxels)
        if (tid < 128) {
            int n = ((b - 2 * RK) << 7) + tid;
            float fa = fp[n] * (1.0f / BETA);
            float fb = fp[Nn + n] * (1.0f / BETA);
            float e = __expf(-0.5f * (fa * fa + fb * fb));
            g_e[n] = e;
            float fi = 1.f, pai = 1.f;
            int r = 0;
#pragma unroll
            for (int i = 0; i <= DEG; i++) {
                if (i > 0) fi *= (float)i;
                float fj = 1.f, pbj = 1.f;
#pragma unroll
                for (int j = 0; j <= DEG - i; j++) {
                    if (j > 0) fj *= (float)j;
                    g_phi[r][n] = rsqrtf(fi * fj) * pai * pbj;
                    pbj *= fb;
                    r++;
                }
                pai *= fa;
            }
            float l0 = lu[n], l1 = lu[Nn + n], l2 = lu[2 * Nn + n], l3 = lu[3 * Nn + n];
            float mx = fmaxf(fmaxf(l0, l1), fmaxf(l2, l3));
            float e0 = __expf(l0 - mx), e1 = __expf(l1 - mx);
            float e2 = __expf(l2 - mx), e3 = __expf(l3 - mx);
            float inv = 1.0f / (e0 + e1 + e2 + e3);
            g_q[0][0][n] = e0 * inv; g_q[0][1][n] = e1 * inv;
            g_q[0][2][n] = e2 * inv; g_q[0][3][n] = e3 * inv;
        }
    }
    gbar(base + (++bk), b, tid);

    // ==== phase C: normalization scales (sum 30 rowsum half-planes) ====
    if (b < 32 && tid < 256) {
        int n = (b << 8) + tid;
        float s = 0.f;
#pragma unroll
        for (int k = 0; k < 2 * RK; k++) s += __ldcg(&g_part[k][n]);
        float e = g_e[n];
        g_pre1[n] = e * rsqrtf(e * s);
        int x = n >> 8, y = (n >> 4) & 15, z = n & 15;
        float Rx = 0.f, Ry = 0.f, Rz = 0.f;
#pragma unroll
        for (int d = 0; d < Xd; d++) Rx += s_wgx[(x > d) ? (x - d) : (d - x)];
#pragma unroll
        for (int d = 0; d < Yd; d++) {
            Ry += s_wgy[(y > d) ? (y - d) : (d - y)];
            Rz += s_wgy[(z > d) ? (z - d) : (d - z)];
        }
        g_pre2[n] = rsqrtf(Rx * Ry * Rz);
    }
    gbar(base + (++bk), b, tid);

    // ==== phase D: psi = phi * pre1 in place ====
    if (b < RK) {
#pragma unroll
        for (int u = 0; u < 8; u++) {
            int n = (u << 10) + tid;
            g_phi[b][n] *= g_pre1[n];
        }
    }
    gbar(base + (++bk), b, tid);

    // ==== phase E: 5 mean-field iterations ====
    bool sp = (task >= RK * Cc);
    int r = sp ? 0 : (task >> 2);
    int c = sp ? (task - RK * Cc) : (task & 3);
    const float4* mul4 = sp ? (const float4*)g_pre2 : (const float4*)g_phi[r];
    const float* wxE = sp ? s_wgx : s_wax;
    const float* wyE = sp ? s_wgy : s_way;
    for (int it = 0; it < NITER; it++) {
        {
            const float4* q4g = (const float4*)g_q[it & 1][c];
            // prologue: psi*q at half positions (1 float4 chunk per thread)
            {
                int line = tid >> 1, q4 = tid & 1;
                int gf4 = (line << 2) + (h << 1) + q4;
                float4 M = mul4[gf4];         // immutable after phase D
                float4 Q = __ldcg(q4g + gf4); // mutable: L2-coherent
                *(float4*)(sm + O_IN + (line << 3) + (q4 << 2)) =
                    make_float4(M.x * Q.x, M.y * Q.y, M.z * Q.z, M.w * Q.w);
            }
            conv3d_half(sm, wxE, wyE, h, tid);
            // epilogue: full-field psi * partial conv
            float4* dst = (float4*)g_part[b];
#pragma unroll
            for (int u = 0; u < 2; u++) {
                int i4 = tid * 2 + u;
                float4 M = mul4[i4];
                int n0 = i4 << 2;
                dst[i4] = make_float4(M.x * CONVOUT(sm, n0),
                                      M.y * CONVOUT(sm, n0 + 1),
                                      M.z * CONVOUT(sm, n0 + 2),
                                      M.w * CONVOUT(sm, n0 + 3));
            }
        }
        gbar(base + (++bk), b, tid);
        // ==== update (R10-proven layout): 32 planes per channel ====
        if (b < 32) {
            int warp = tid >> 5, lane = tid & 31;
            int uc = warp & 3;
            int ulv = ((warp >> 2) << 5) + lane;
            int un = (b << 8) + ulv;
            float u = 0.f;
#pragma unroll
            for (int rr = 0; rr < RK; rr++) {
                u += __ldcg(&g_part[(rr * 4 + uc) * 2 + 0][un]);
                u += __ldcg(&g_part[(rr * 4 + uc) * 2 + 1][un]);
            }
            u += __ldcg(&g_part[(RK * 4 + uc) * 2 + 0][un]);
            u += __ldcg(&g_part[(RK * 4 + uc) * 2 + 1][un]);
            sm[O_IN + uc * 256 + ulv] = u;
            __syncthreads();
            float u0 = sm[O_IN + 0 * 256 + ulv], u1 = sm[O_IN + 1 * 256 + ulv];
            float u2 = sm[O_IN + 2 * 256 + ulv], u3 = sm[O_IN + 3 * 256 + ulv];
            float lg0 = lu[un]          - (s_cmp[0] * u0 + s_cmp[1] * u1 + s_cmp[2] * u2 + s_cmp[3] * u3);
            float lg1 = lu[Nn + un]     - (s_cmp[4] * u0 + s_cmp[5] * u1 + s_cmp[6] * u2 + s_cmp[7] * u3);
            float lg2 = lu[2 * Nn + un] - (s_cmp[8] * u0 + s_cmp[9] * u1 + s_cmp[10] * u2 + s_cmp[11] * u3);
            float lg3 = lu[3 * Nn + un] - (s_cmp[12] * u0 + s_cmp[13] * u1 + s_cmp[14] * u2 + s_cmp[15] * u3);
            float mx = fmaxf(fmaxf(lg0, lg1), fmaxf(lg2, lg3));
            float e0 = __expf(lg0 - mx), e1 = __expf(lg1 - mx);
            float e2 = __expf(lg2 - mx), e3 = __expf(lg3 - mx);
            float inv = 1.0f / (e0 + e1 + e2 + e3);
            float qv = (uc == 0 ? e0 : uc == 1 ? e1 : uc == 2 ? e2 : e3) * inv;
            if (it == NITER - 1) out[uc * Nn + un] = qv;
            else                 g_q[(it + 1) & 1][uc][un] = qv;
        }
        if (it < NITER - 1) gbar(base + (++bk), b, tid);
    }
}

extern "C" void kernel_launch(void* const* d_in, const int* in_sizes, int n_in,
                              void* d_out, int out_size) {
    const float* lu   = (const float*)d_in[0];
    const float* fp   = (const float*)d_in[1];
    const float* comp = (const float*)d_in[2];
    float* out = (float*)d_out;

    cudaFuncSetAttribute(k_crf, cudaFuncAttributeMaxDynamicSharedMemorySize, SMEM_BYTES);
    k_crf<<<NBLK, 1024, SMEM_BYTES>>>(lu, fp, comp, out);
}

// round 14
// speedup vs baseline: 1.3407x; 1.1005x over previous
#include <cuda_runtime.h>
#include <math.h>

#define Xd 32
#define Yd 16
#define Nn 8192          // 32*16*16
#define Cc 4
#define NITER 5
#define BETA  5.0f
#define DEG 4            // Taylor truncation (rel_err insensitive through DEG4)
#define RK 15            // #(i,j), i+j<=4
#define NTASK (RK * Cc + Cc)  // 64 conv tasks
#define NBLK (NTASK * 2)      // 128 blocks: 2 per task (input z-halves)

// shared layout (float offsets)
#define O_IN  0                 // 4096: input half field, idx = line*8 + zl
#define O_CX  4096              // 4352: conv-x out, idx = x*136 + y*8 + zl
#define O_CY  8448              // 5632: conv-y out, idx = (x*16+y)*11 + zl
#define O_CZ  14080             // 8704: conv-z out (full), idx = line*17 + z
#define O_TBL 22784
#define SMEM_FLOATS (22784 + 32)
#define SMEM_BYTES (SMEM_FLOATS * 4)

// Gaussian taps exp(-d*d/50) for ALPHA == GAMMA == 5.0 (compile-time constants)
__device__ constexpr float WT[32] = {
    1.000000000f, 0.980198673f, 0.923116346f, 0.835270211f,
    0.726149037f, 0.606530660f, 0.486752256f, 0.375311099f,
    0.278037300f, 0.197898699f, 0.135335283f, 0.0889216175f,
    0.0561347628f, 0.0340474547f, 0.0198410947f, 0.0111089965f,
    0.00597602290f, 0.00308871541f, 0.00153381068f, 0.000731802419f,
    0.000335462628f, 0.000147747400f, 6.25215038e-5f, 2.54193465e-5f,
    9.92950431e-6f, 3.72665317e-6f, 1.34381228e-6f, 4.65571000e-7f,
    1.54976000e-7f, 4.95642000e-8f, 1.52299797e-8f, 4.49638000e-9f
};

__host__ __device__ constexpr int cabs(int v) { return v < 0 ? -v : v; }

// ---- static device scratch ----
__device__ float g_phi[RK][Nn];      // immutable after phase A
__device__ float g_e[Nn];
__device__ float g_pre1[Nn];
__device__ float g_pre2[Nn];
__device__ float g_part[NBLK][Nn];   // per-block partial planes
__device__ float g_q[2][Cc][Nn];
__device__ unsigned g_arr[NBLK];
__device__ unsigned g_gen;

// ---- observer grid barrier (proven) ----
__device__ __forceinline__ void gbar(unsigned tgt, int b, int tid) {
    __syncthreads();
    if (b == 0) {
        if (tid == 0) { __threadfence(); *(volatile unsigned*)&g_arr[0] = tgt; }
        if (tid < NBLK) { while (*(volatile unsigned*)&g_arr[tid] < tgt) { } }
        __syncthreads();
        if (tid == 0) { __threadfence(); *(volatile unsigned*)&g_gen = tgt; }
    } else {
        if (tid == 0) {
            __threadfence();
            *(volatile unsigned*)&g_arr[b] = tgt;
            while (*(volatile unsigned*)&g_gen < tgt) { }
            __threadfence();
        }
        __syncthreads();
    }
}

// ==== template-recursive conv steps: weight index is a template constant ====
// conv-x
template<int XG, int XP> struct CXs {
    static __device__ __forceinline__ void run(const float* sI, int pos, float* a) {
        float v = sI[(XP << 7) + pos];
        a[0] += WT[cabs(XG + 0 - XP)] * v;
        a[1] += WT[cabs(XG + 1 - XP)] * v;
        a[2] += WT[cabs(XG + 2 - XP)] * v;
        a[3] += WT[cabs(XG + 3 - XP)] * v;
        CXs<XG, XP + 1>::run(sI, pos, a);
    }
};
template<int XG> struct CXs<XG, 32> {
    static __device__ __forceinline__ void run(const float*, int, float*) {}
};
template<int XG>
__device__ __forceinline__ void conv_x_one(const float* sI, float* sX, int pos) {
    float a[4] = {0.f, 0.f, 0.f, 0.f};
    CXs<XG, 0>::run(sI, pos, a);
#pragma unroll
    for (int k = 0; k < 4; k++) sX[(XG + k) * 136 + pos] = a[k];
}
// conv-y
template<int YG, int YP> struct CYs {
    static __device__ __forceinline__ void run(const float* sX, int x, int zl, float* a) {
        float v = sX[x * 136 + (YP << 3) + zl];
        a[0] += WT[cabs(YG + 0 - YP)] * v;
        a[1] += WT[cabs(YG + 1 - YP)] * v;
        a[2] += WT[cabs(YG + 2 - YP)] * v;
        a[3] += WT[cabs(YG + 3 - YP)] * v;
        CYs<YG, YP + 1>::run(sX, x, zl, a);
    }
};
template<int YG> struct CYs<YG, 16> {
    static __device__ __forceinline__ void run(const float*, int, int, float*) {}
};
template<int YG>
__device__ __forceinline__ void conv_y_one(const float* sX, float* sY, int x, int zl) {
    float a[4] = {0.f, 0.f, 0.f, 0.f};
    CYs<YG, 0>::run(sX, x, zl, a);
#pragma unroll
    for (int k = 0; k < 4; k++) sY[(x * 16 + YG + k) * 11 + zl] = a[k];
}
// conv-z (partial over input z-half; ZB = ZG - 8h may be negative)
template<int ZB, int ZL> struct CZs {
    static __device__ __forceinline__ void run(const float* in, float* a) {
        float v = in[ZL];
        a[0] += WT[cabs(ZB + 0 - ZL)] * v;
        a[1] += WT[cabs(ZB + 1 - ZL)] * v;
        a[2] += WT[cabs(ZB + 2 - ZL)] * v;
        a[3] += WT[cabs(ZB + 3 - ZL)] * v;
        a[4] += WT[cabs(ZB + 4 - ZL)] * v;
        a[5] += WT[cabs(ZB + 5 - ZL)] * v;
        a[6] += WT[cabs(ZB + 6 - ZL)] * v;
        a[7] += WT[cabs(ZB + 7 - ZL)] * v;
        CZs<ZB, ZL + 1>::run(in, a);
    }
};
template<int ZB> struct CZs<ZB, 8> {
    static __device__ __forceinline__ void run(const float*, float*) {}
};
template<int ZG, int ZB>
__device__ __forceinline__ void conv_z_one(const float* sY, float* sZ, int line) {
    float a[8] = {0.f,0.f,0.f,0.f,0.f,0.f,0.f,0.f};
    CZs<ZB, 0>::run(sY + line * 11, a);
#pragma unroll
    for (int k = 0; k < 8; k++) sZ[line * 17 + ZG + k] = a[k];
}

// ---- half-input separable conv: sm[O_IN] (z-half h) -> sm[O_CZ] (full-z partial) ----
__device__ __forceinline__ void conv3d_half(float* sm, int h, int tid) {
    float* sI = sm + O_IN;
    float* sX = sm + O_CX;
    float* sY = sm + O_CY;
    float* sZ = sm + O_CZ;
    __syncthreads();
    // conv-x: 8 warp-uniform groups of 4 x-outputs, 128 (y,zl) positions each
    {
        int pos = tid & 127;
        switch (tid >> 7) {
            case 0: conv_x_one<0 >(sI, sX, pos); break;
            case 1: conv_x_one<4 >(sI, sX, pos); break;
            case 2: conv_x_one<8 >(sI, sX, pos); break;
            case 3: conv_x_one<12>(sI, sX, pos); break;
            case 4: conv_x_one<16>(sI, sX, pos); break;
            case 5: conv_x_one<20>(sI, sX, pos); break;
            case 6: conv_x_one<24>(sI, sX, pos); break;
            default: conv_x_one<28>(sI, sX, pos); break;
        }
    }
    __syncthreads();
    // conv-y: 4 warp-uniform groups of 4 y-outputs; pos = (x, zl)
    {
        int pos = tid & 255;
        int x = pos >> 3, zl = pos & 7;
        switch (tid >> 8) {
            case 0: conv_y_one<0 >(sX, sY, x, zl); break;
            case 1: conv_y_one<4 >(sX, sY, x, zl); break;
            case 2: conv_y_one<8 >(sX, sY, x, zl); break;
            default: conv_y_one<12>(sX, sY, x, zl); break;
        }
    }
    __syncthreads();
    // conv-z: 2 warp-uniform z-output groups x 512 lines; ZB = ZG - 8h
    {
        int line = tid & 511;
        if (h == 0) {
            if (tid < 512) conv_z_one<0, 0>(sY, sZ, line);
            else           conv_z_one<8, 8>(sY, sZ, line);
        } else {
            if (tid < 512) conv_z_one<0, -8>(sY, sZ, line);
            else           conv_z_one<8, 0>(sY, sZ, line);
        }
    }
    __syncthreads();
}

#define CONVOUT(sm, n) ((sm)[O_CZ + ((n) >> 4) * 17 + ((n) & 15)])

__global__ __launch_bounds__(1024, 1) void k_crf(
    const float* __restrict__ lu, const float* __restrict__ fp,
    const float* __restrict__ comp, float* __restrict__ out) {
    extern __shared__ float sm[];
    float* s_cmp = sm + O_TBL;
    __shared__ unsigned s_base;

    int tid = threadIdx.x;
    int b = blockIdx.x;

    if (tid == 0) s_base = *(volatile unsigned*)&g_arr[b];
    if (tid < 16) s_cmp[tid] = comp[tid];
    __syncthreads();
    unsigned base = s_base, bk = 0;

    int task = b >> 1, h = b & 1;

    // ==== phase A || B ====
    if (b < 2 * RK) {
        // B: partial rowsum conv for rank (task), input half h
        int i = 0, rr = task;
        while (rr > DEG - i) { rr -= DEG - i + 1; i++; }
        int j = rr;
        float fi = 1.f, fj = 1.f;
        for (int t = 2; t <= i; t++) fi *= (float)t;
        for (int t = 2; t <= j; t++) fj *= (float)t;
        float coef = rsqrtf(fi * fj);
        {
            int line = tid >> 1, q4 = tid & 1;
            int n0 = ((line << 2) + (h << 1) + q4) << 2;
#pragma unroll
            for (int el = 0; el < 4; el++) {
                int n = n0 + el;
                float fa = fp[n] * (1.0f / BETA);
                float fb = fp[Nn + n] * (1.0f / BETA);
                float e = __expf(-0.5f * (fa * fa + fb * fb));
                float pa = 1.f, pb = 1.f;
                for (int t = 0; t < i; t++) pa *= fa;
                for (int t = 0; t < j; t++) pb *= fb;
                sm[O_IN + (line << 3) + (q4 << 2) + el] = coef * pa * pb * e;
            }
        }
        conv3d_half(sm, h, tid);
#pragma unroll
        for (int u = 0; u < 2; u++) {
            int n0 = (tid * 2 + u) << 2;
#pragma unroll
            for (int el = 0; el < 4; el++) {
                int n = n0 + el;
                float fa = fp[n] * (1.0f / BETA);
                float fb = fp[Nn + n] * (1.0f / BETA);
                float pa = 1.f, pb = 1.f;
                for (int t = 0; t < i; t++) pa *= fa;
                for (int t = 0; t < j; t++) pb *= fb;
                g_part[b][n] = coef * pa * pb * CONVOUT(sm, n);
            }
        }
    } else if (b < 2 * RK + 64) {
        // A: phi basis, e, q0
        if (tid < 128) {
            int n = ((b - 2 * RK) << 7) + tid;
            float fa = fp[n] * (1.0f / BETA);
            float fb = fp[Nn + n] * (1.0f / BETA);
            float e = __expf(-0.5f * (fa * fa + fb * fb));
            g_e[n] = e;
            float fi = 1.f, pai = 1.f;
            int r = 0;
#pragma unroll
            for (int i = 0; i <= DEG; i++) {
                if (i > 0) fi *= (float)i;
                float fj = 1.f, pbj = 1.f;
#pragma unroll
                for (int j = 0; j <= DEG - i; j++) {
                    if (j > 0) fj *= (float)j;
                    g_phi[r][n] = rsqrtf(fi * fj) * pai * pbj;
                    pbj *= fb;
                    r++;
                }
                pai *= fa;
            }
            float l0 = lu[n], l1 = lu[Nn + n], l2 = lu[2 * Nn + n], l3 = lu[3 * Nn + n];
            float mx = fmaxf(fmaxf(l0, l1), fmaxf(l2, l3));
            float e0 = __expf(l0 - mx), e1 = __expf(l1 - mx);
            float e2 = __expf(l2 - mx), e3 = __expf(l3 - mx);
            float inv = 1.0f / (e0 + e1 + e2 + e3);
            g_q[0][0][n] = e0 * inv; g_q[0][1][n] = e1 * inv;
            g_q[0][2][n] = e2 * inv; g_q[0][3][n] = e3 * inv;
        }
    }
    gbar(base + (++bk), b, tid);

    // ==== phase C: normalization scales ====
    if (b < 32 && tid < 256) {
        int n = (b << 8) + tid;
        float s = 0.f;
#pragma unroll
        for (int k = 0; k < 2 * RK; k++) s += __ldcg(&g_part[k][n]);
        float e = g_e[n];
        g_pre1[n] = e * rsqrtf(e * s);
        int x = n >> 8, y = (n >> 4) & 15, z = n & 15;
        float Rx = 0.f, Ry = 0.f, Rz = 0.f;
#pragma unroll
        for (int d = 0; d < Xd; d++) Rx += WT[(x > d) ? (x - d) : (d - x)];
#pragma unroll
        for (int d = 0; d < Yd; d++) {
            Ry += WT[(y > d) ? (y - d) : (d - y)];
            Rz += WT[(z > d) ? (z - d) : (d - z)];
        }
        g_pre2[n] = rsqrtf(Rx * Ry * Rz);
    }
    gbar(base + (++bk), b, tid);

    // ==== phase E: 5 mean-field iterations (pre1 folded on the fly; no phase D) ====
    bool sp = (task >= RK * Cc);
    int r = sp ? 0 : (task >> 2);
    int c = sp ? (task - RK * Cc) : (task & 3);
    const float4* phi4  = (const float4*)g_phi[r];    // immutable after A
    const float4* pre14 = (const float4*)g_pre1;      // immutable after C
    const float4* pre24 = (const float4*)g_pre2;
    for (int it = 0; it < NITER; it++) {
        {
            const float4* q4g = (const float4*)g_q[it & 1][c];
            // prologue: M = (phi*pre1 | pre2) * q on half positions
            {
                int line = tid >> 1, q4 = tid & 1;
                int gf4 = (line << 2) + (h << 1) + q4;
                float4 Q = __ldcg(q4g + gf4);
                float4 M;
                if (sp) M = pre24[gf4];
                else {
                    float4 A = phi4[gf4], P = pre14[gf4];
                    M = make_float4(A.x * P.x, A.y * P.y, A.z * P.z, A.w * P.w);
                }
                *(float4*)(sm + O_IN + (line << 3) + (q4 << 2)) =
                    make_float4(M.x * Q.x, M.y * Q.y, M.z * Q.z, M.w * Q.w);
            }
            conv3d_half(sm, h, tid);
            // epilogue: full-field multiplier * partial conv
            float4* dst = (float4*)g_part[b];
#pragma unroll
            for (int u = 0; u < 2; u++) {
                int i4 = tid * 2 + u;
                float4 M;
                if (sp) M = pre24[i4];
                else {
                    float4 A = phi4[i4], P = pre14[i4];
                    M = make_float4(A.x * P.x, A.y * P.y, A.z * P.z, A.w * P.w);
                }
                int n0 = i4 << 2;
                dst[i4] = make_float4(M.x * CONVOUT(sm, n0),
                                      M.y * CONVOUT(sm, n0 + 1),
                                      M.z * CONVOUT(sm, n0 + 2),
                                      M.w * CONVOUT(sm, n0 + 3));
            }
        }
        gbar(base + (++bk), b, tid);
        // ==== update (R10/R13-proven): 32 planes per channel ====
        if (b < 32) {
            int warp = tid >> 5, lane = tid & 31;
            int uc = warp & 3;
            int ulv = ((warp >> 2) << 5) + lane;
            int un = (b << 8) + ulv;
            float u = 0.f;
#pragma unroll
            for (int rr = 0; rr < RK; rr++) {
                u += __ldcg(&g_part[(rr * 4 + uc) * 2 + 0][un]);
                u += __ldcg(&g_part[(rr * 4 + uc) * 2 + 1][un]);
            }
            u += __ldcg(&g_part[(RK * 4 + uc) * 2 + 0][un]);
            u += __ldcg(&g_part[(RK * 4 + uc) * 2 + 1][un]);
            sm[O_IN + uc * 256 + ulv] = u;
            __syncthreads();
            float u0 = sm[O_IN + 0 * 256 + ulv], u1 = sm[O_IN + 1 * 256 + ulv];
            float u2 = sm[O_IN + 2 * 256 + ulv], u3 = sm[O_IN + 3 * 256 + ulv];
            float lg0 = lu[un]          - (s_cmp[0] * u0 + s_cmp[1] * u1 + s_cmp[2] * u2 + s_cmp[3] * u3);
            float lg1 = lu[Nn + un]     - (s_cmp[4] * u0 + s_cmp[5] * u1 + s_cmp[6] * u2 + s_cmp[7] * u3);
            float lg2 = lu[2 * Nn + un] - (s_cmp[8] * u0 + s_cmp[9] * u1 + s_cmp[10] * u2 + s_cmp[11] * u3);
            float lg3 = lu[3 * Nn + un] - (s_cmp[12] * u0 + s_cmp[13] * u1 + s_cmp[14] * u2 + s_cmp[15] * u3);
            float mx = fmaxf(fmaxf(lg0, lg1), fmaxf(lg2, lg3));
            float e0 = __expf(lg0 - mx), e1 = __expf(lg1 - mx);
            float e2 = __expf(lg2 - mx), e3 = __expf(lg3 - mx);
            float inv = 1.0f / (e0 + e1 + e2 + e3);
            float qv = (uc == 0 ? e0 : uc == 1 ? e1 : uc == 2 ? e2 : e3) * inv;
            if (it == NITER - 1) out[uc * Nn + un] = qv;
            else                 g_q[(it + 1) & 1][uc][un] = qv;
        }
        if (it < NITER - 1) gbar(base + (++bk), b, tid);
    }
}

extern "C" void kernel_launch(void* const* d_in, const int* in_sizes, int n_in,
                              void* d_out, int out_size) {
    const float* lu   = (const float*)d_in[0];
    const float* fp   = (const float*)d_in[1];
    const float* comp = (const float*)d_in[2];
    float* out = (float*)d_out;

    cudaFuncSetAttribute(k_crf, cudaFuncAttributeMaxDynamicSharedMemorySize, SMEM_BYTES);
    k_crf<<<NBLK, 1024, SMEM_BYTES>>>(lu, fp, comp, out);
}